// round 6
// baseline (speedup 1.0000x reference)
#include <cuda_runtime.h>

// DeEmphasis: y[n] = x[n] + ALPHA*y[n-1], zero init, rows of 960000 fp32.
//
// R6: R2 structure (best DRAM%: warp-autonomous spans, multi-wave so CTA
// spread is absorbed by the scheduler) with two changes:
//  - __stwt (write-through) stores: no dirty L2 lines left behind, so
//    back-to-back graph replays don't pay dirty-eviction writebacks ahead
//    of every fresh read fill.
//  - halo cut to 1 group (alpha^128 ~ 9.2e-10, far below 1e-3 tolerance):
//    read overhead 3.3% -> 1.7%.
// Per 128-elem group: lane holds float4 (coalesced 512B), 3-FMA local scan,
// 5-step warp Kogge-Stone affine scan (coef alpha^4), recompute from true
// entering state, float4 store. 4-wide unrolled body -> MLP 4 per warp.

#define ALPHA 0.85f

static constexpr int ROWLEN  = 960000;
static constexpr int P       = 7680;           // payload per warp (60 groups)
static constexpr int H       = 128;            // halo = 1 group
static constexpr int SPANS   = ROWLEN / P;     // 125 spans per row
static constexpr int WPB     = 4;              // warps per block
static constexpr int THREADS = WPB * 32;       // 128
static constexpr int MAIN_ITERS = P / 128;     // 60 (divisible by 4)

// compile-time alpha^n (double accumulation, rounded once)
__host__ __device__ constexpr float apow(int n) {
    double r = 1.0;
    for (int i = 0; i < n; i++) r *= (double)ALPHA;
    return (float)r;
}

// Process one 128-element group (4 consecutive elems per lane).
// c: warp-entering filter state (updated). Returns the 4 outputs.
__device__ __forceinline__ float4 proc128(float4 v, float AL, float& c, int lane)
{
    const float A    = ALPHA;
    const float A4   = apow(4);
    const float A128 = apow(128);

    // local inclusive scan of the lane's 4 elements (zero entering)
    float l1 = fmaf(A, v.x, v.y);
    float l2 = fmaf(A, l1, v.z);
    float l3 = fmaf(A, l2, v.w);

    // warp Kogge-Stone affine scan over lane totals, per-lane coef alpha^4
    float s = l3, cp = A4;
    #pragma unroll
    for (int d = 1; d < 32; d <<= 1) {
        float u = __shfl_up_sync(0xffffffffu, s, d);
        if (lane >= d) s = fmaf(cp, u, s);
        cp *= cp;
    }
    float wtot = __shfl_sync(0xffffffffu, s, 31);     // warp total (zero entry)
    float e    = __shfl_up_sync(0xffffffffu, s, 1);   // state entering my 4-seg
    if (lane == 0) e = 0.0f;

    // true entering state for this lane's segment: e + alpha^(4*lane) * c
    float enter = fmaf(AL, c, e);

    float4 o;
    o.x = fmaf(A, enter, v.x);
    o.y = fmaf(A, o.x,  v.y);
    o.z = fmaf(A, o.y,  v.z);
    o.w = fmaf(A, o.z,  v.w);

    c = fmaf(A128, c, wtot);    // carry into next 128-group
    return o;
}

__global__ void __launch_bounds__(THREADS, 10)
deemph_kernel(const float* __restrict__ x, float* __restrict__ y, int nwarps)
{
    const int gw = blockIdx.x * WPB + (threadIdx.x >> 5);
    if (gw >= nwarps) return;
    const int lane = threadIdx.x & 31;
    const int row  = gw / SPANS;
    const int span = gw - row * SPANS;

    // per-lane constant alpha^(4*lane) via 5 conditional multiplies
    float AL = 1.0f;
    if (lane & 1)  AL *= apow(4);
    if (lane & 2)  AL *= apow(8);
    if (lane & 4)  AL *= apow(16);
    if (lane & 8)  AL *= apow(32);
    if (lane & 16) AL *= apow(64);

    const float* px = x + row * ROWLEN + span * P + lane * 4;
    float*       py = y + row * ROWLEN + span * P + lane * 4;

    float c = 0.0f;

    // halo warm-up: 1 group before the payload (span 0 has true zero history)
    if (span > 0) {
        float4 h = __ldcs((const float4*)(px - H));
        (void)proc128(h, AL, c, lane);
    }

    // main: 60 groups, 4-wide pipelined (independent loads + shfl chains)
    #pragma unroll 1
    for (int k = 0; k < MAIN_ITERS; k += 4) {
        const float* p = px + k * 128;
        float4 v0 = __ldcs((const float4*)(p));
        float4 v1 = __ldcs((const float4*)(p + 128));
        float4 v2 = __ldcs((const float4*)(p + 256));
        float4 v3 = __ldcs((const float4*)(p + 384));

        float4 o0 = proc128(v0, AL, c, lane);
        float4 o1 = proc128(v1, AL, c, lane);
        float4 o2 = proc128(v2, AL, c, lane);
        float4 o3 = proc128(v3, AL, c, lane);

        float* q = py + k * 128;
        __stwt((float4*)(q),       o0);
        __stwt((float4*)(q + 128), o1);
        __stwt((float4*)(q + 256), o2);
        __stwt((float4*)(q + 384), o3);
    }
}

extern "C" void kernel_launch(void* const* d_in, const int* in_sizes, int n_in,
                              void* d_out, int out_size)
{
    const float* x = (const float*)d_in[0];
    float*       y = (float*)d_out;

    const int n      = in_sizes[0];        // 61,440,000
    const int rows   = n / ROWLEN;         // 64
    const int nwarps = rows * SPANS;       // 8000
    const int blocks = (nwarps + WPB - 1) / WPB;   // 2000

    deemph_kernel<<<blocks, THREADS>>>(x, y, nwarps);
}

// round 7
// speedup vs baseline: 1.0334x; 1.0334x over previous
#include <cuda_runtime.h>

// DeEmphasis: y[n] = x[n] + ALPHA*y[n-1], zero init, rows of 960000 fp32.
//
// R7: R6 structure, NO cache hints. Isolated variable: every kernel that
// benched well used default-cached ld/st; __ldcs/__stcs guarantee zero L2
// retention across graph replays (492MB footprint vs 126MB L2 -> random
// replacement retains ~25% with default policy, 0% with evict-first).
// ncu (--cache-control all, cold) is blind to this; the bench loop is not.
//
// Structure: warp-autonomous spans, payload 7680 + 1-group halo (alpha^128
// ~ 9.2e-10, below fp32 noise). Per 128-elem group: lane holds float4
// (coalesced 512B/warp), 3-FMA local scan, 5-step warp Kogge-Stone affine
// scan (coef alpha^4), recompute from true entering state, float4 store.
// 4-wide unrolled body -> 4 outstanding LDG.128 per warp.

#define ALPHA 0.85f

static constexpr int ROWLEN  = 960000;
static constexpr int P       = 7680;           // payload per warp (60 groups)
static constexpr int H       = 128;            // halo = 1 group
static constexpr int SPANS   = ROWLEN / P;     // 125 spans per row
static constexpr int WPB     = 4;              // warps per block
static constexpr int THREADS = WPB * 32;       // 128
static constexpr int MAIN_ITERS = P / 128;     // 60 (divisible by 4)

// compile-time alpha^n (double accumulation, rounded once)
__host__ __device__ constexpr float apow(int n) {
    double r = 1.0;
    for (int i = 0; i < n; i++) r *= (double)ALPHA;
    return (float)r;
}

// Process one 128-element group (4 consecutive elems per lane).
// c: warp-entering filter state (updated). Returns the 4 outputs.
__device__ __forceinline__ float4 proc128(float4 v, float AL, float& c, int lane)
{
    const float A    = ALPHA;
    const float A4   = apow(4);
    const float A128 = apow(128);

    // local inclusive scan of the lane's 4 elements (zero entering)
    float l1 = fmaf(A, v.x, v.y);
    float l2 = fmaf(A, l1, v.z);
    float l3 = fmaf(A, l2, v.w);

    // warp Kogge-Stone affine scan over lane totals, per-lane coef alpha^4
    float s = l3, cp = A4;
    #pragma unroll
    for (int d = 1; d < 32; d <<= 1) {
        float u = __shfl_up_sync(0xffffffffu, s, d);
        if (lane >= d) s = fmaf(cp, u, s);
        cp *= cp;
    }
    float wtot = __shfl_sync(0xffffffffu, s, 31);     // warp total (zero entry)
    float e    = __shfl_up_sync(0xffffffffu, s, 1);   // state entering my 4-seg
    if (lane == 0) e = 0.0f;

    // true entering state for this lane's segment: e + alpha^(4*lane) * c
    float enter = fmaf(AL, c, e);

    float4 o;
    o.x = fmaf(A, enter, v.x);
    o.y = fmaf(A, o.x,  v.y);
    o.z = fmaf(A, o.y,  v.z);
    o.w = fmaf(A, o.z,  v.w);

    c = fmaf(A128, c, wtot);    // carry into next 128-group
    return o;
}

__global__ void __launch_bounds__(THREADS, 10)
deemph_kernel(const float* __restrict__ x, float* __restrict__ y, int nwarps)
{
    const int gw = blockIdx.x * WPB + (threadIdx.x >> 5);
    if (gw >= nwarps) return;
    const int lane = threadIdx.x & 31;
    const int row  = gw / SPANS;
    const int span = gw - row * SPANS;

    // per-lane constant alpha^(4*lane) via 5 conditional multiplies
    float AL = 1.0f;
    if (lane & 1)  AL *= apow(4);
    if (lane & 2)  AL *= apow(8);
    if (lane & 4)  AL *= apow(16);
    if (lane & 8)  AL *= apow(32);
    if (lane & 16) AL *= apow(64);

    const float* px = x + row * ROWLEN + span * P + lane * 4;
    float*       py = y + row * ROWLEN + span * P + lane * 4;

    float c = 0.0f;

    // halo warm-up: 1 group before the payload (span 0 has true zero history)
    if (span > 0) {
        float4 h = *((const float4*)(px - H));
        (void)proc128(h, AL, c, lane);
    }

    // main: 60 groups, 4-wide pipelined (independent loads + shfl chains)
    #pragma unroll 1
    for (int k = 0; k < MAIN_ITERS; k += 4) {
        const float* p = px + k * 128;
        float4 v0 = *((const float4*)(p));
        float4 v1 = *((const float4*)(p + 128));
        float4 v2 = *((const float4*)(p + 256));
        float4 v3 = *((const float4*)(p + 384));

        float4 o0 = proc128(v0, AL, c, lane);
        float4 o1 = proc128(v1, AL, c, lane);
        float4 o2 = proc128(v2, AL, c, lane);
        float4 o3 = proc128(v3, AL, c, lane);

        float* q = py + k * 128;
        *((float4*)(q))       = o0;
        *((float4*)(q + 128)) = o1;
        *((float4*)(q + 256)) = o2;
        *((float4*)(q + 384)) = o3;
    }
}

extern "C" void kernel_launch(void* const* d_in, const int* in_sizes, int n_in,
                              void* d_out, int out_size)
{
    const float* x = (const float*)d_in[0];
    float*       y = (float*)d_out;

    const int n      = in_sizes[0];        // 61,440,000
    const int rows   = n / ROWLEN;         // 64
    const int nwarps = rows * SPANS;       // 8000
    const int blocks = (nwarps + WPB - 1) / WPB;   // 2000

    deemph_kernel<<<blocks, THREADS>>>(x, y, nwarps);
}

// round 8
// speedup vs baseline: 1.0487x; 1.0148x over previous
#include <cuda_runtime.h>

// DeEmphasis: y[n] = x[n] + ALPHA*y[n-1], zero init, rows of 960000 fp32.
//
// R8: R1's winning macro structure (256-thread blocks, phase-separated
// 31KB pure-read burst -> compute -> 30KB pure-write burst, plain cached
// ld/st) with R1's micro overheads removed:
//  - float4 staging both directions (4x fewer L1 transactions, no padding)
//  - compute via warp Kogge-Stone affine scan reading float4 from smem in
//    the staged layout (no layout conversion). Cross-warp carry handled by
//    each warp warming up on the 2 groups (256 elems, alpha^256 ~ 8.5e-19)
//    preceding its sub-span -- extra compute only, no extra DRAM traffic.
// Block owns CHUNK=7680 payload + HALO=256; grid (125, 64) = 8000 blocks.

#define ALPHA 0.85f

static constexpr int ROWLEN  = 960000;
static constexpr int CHUNK   = 7680;            // 60 groups of 128
static constexpr int HALO    = 256;             // 2 groups
static constexpr int TOTAL   = CHUNK + HALO;    // 7936 floats = 31 KB
static constexpr int THREADS = 256;
static constexpr int NWARP   = 8;
static constexpr int PGROUPS = CHUNK / 128;     // 60
static constexpr int NV_IN   = TOTAL / 4;       // 1984 float4
static constexpr int NV_OUT  = CHUNK / 4;       // 1920 float4

// compile-time alpha^n (double accumulation, rounded once)
__host__ __device__ constexpr float apow(int n) {
    double r = 1.0;
    for (int i = 0; i < n; i++) r *= (double)ALPHA;
    return (float)r;
}

// Process one 128-element group (4 consecutive elems per lane).
// c: entering filter state (updated). Returns the 4 outputs.
__device__ __forceinline__ float4 proc128(float4 v, float AL, float& c, int lane)
{
    const float A    = ALPHA;
    const float A4   = apow(4);
    const float A128 = apow(128);

    // local inclusive scan of the lane's 4 elements (zero entering)
    float l1 = fmaf(A, v.x, v.y);
    float l2 = fmaf(A, l1, v.z);
    float l3 = fmaf(A, l2, v.w);

    // warp Kogge-Stone affine scan over lane totals, per-lane coef alpha^4
    float s = l3, cp = A4;
    #pragma unroll
    for (int d = 1; d < 32; d <<= 1) {
        float u = __shfl_up_sync(0xffffffffu, s, d);
        if (lane >= d) s = fmaf(cp, u, s);
        cp *= cp;
    }
    float wtot = __shfl_sync(0xffffffffu, s, 31);     // group total (zero entry)
    float e    = __shfl_up_sync(0xffffffffu, s, 1);   // state entering my 4-seg
    if (lane == 0) e = 0.0f;

    // true entering state for this lane's segment: e + alpha^(4*lane) * c
    float enter = fmaf(AL, c, e);

    float4 o;
    o.x = fmaf(A, enter, v.x);
    o.y = fmaf(A, o.x,  v.y);
    o.z = fmaf(A, o.y,  v.z);
    o.w = fmaf(A, o.z,  v.w);

    c = fmaf(A128, c, wtot);    // carry into next 128-group
    return o;
}

__global__ void __launch_bounds__(THREADS, 4)
deemph_kernel(const float* __restrict__ x, float* __restrict__ y)
{
    __shared__ float4 s4[NV_IN];
    float* s = (float*)s4;

    const int chunk = blockIdx.x;          // 0..124
    const int row   = blockIdx.y;          // 0..63
    const int tid   = threadIdx.x;
    const int lane  = tid & 31;
    const int w     = tid >> 5;

    const int gbase = row * ROWLEN + chunk * CHUNK - HALO;  // float idx of s[0]

    // ---- phase 1: 31KB pure-read burst, float4 coalesced, flat layout ----
    #pragma unroll
    for (int p = 0; p < 8; p++) {
        int idx = tid + p * THREADS;
        if (idx < NV_IN) {
            float4 v;
            if (chunk == 0 && idx < HALO / 4)
                v = make_float4(0.f, 0.f, 0.f, 0.f);     // per-row zero history
            else
                v = *(const float4*)(x + gbase + idx * 4);
            s4[idx] = v;
        }
    }
    __syncthreads();

    // per-lane constant alpha^(4*lane) via 5 conditional multiplies
    float AL = 1.0f;
    if (lane & 1)  AL *= apow(4);
    if (lane & 2)  AL *= apow(8);
    if (lane & 4)  AL *= apow(16);
    if (lane & 8)  AL *= apow(32);
    if (lane & 16) AL *= apow(64);

    // warp w owns payload groups [g0, g1): 7 or 8 groups
    const int g0 = (PGROUPS * w) / NWARP;
    const int g1 = (PGROUPS * (w + 1)) / NWARP;

    float c = 0.0f;

    // warm-up: the 2 groups preceding g0 (smem offsets g0*128, (g0+1)*128,
    // since payload group g lives at HALO + g*128 and HALO = 2*128).
    {
        float4 h0 = *(const float4*)(s + g0 * 128 + lane * 4);
        float4 h1 = *(const float4*)(s + (g0 + 1) * 128 + lane * 4);
        (void)proc128(h0, AL, c, lane);
        (void)proc128(h1, AL, c, lane);
    }
    // warps read neighbors' payload regions during warm-up; sync before the
    // in-place overwrite below.
    __syncthreads();

    // ---- phase 2: compute, in-place in smem (read group, write outputs) ----
    #pragma unroll 4
    for (int g = g0; g < g1; g++) {
        float* sp = s + HALO + g * 128 + lane * 4;
        float4 v = *(const float4*)sp;
        float4 o = proc128(v, AL, c, lane);
        *(float4*)sp = o;
    }
    __syncthreads();

    // ---- phase 3: 30KB pure-write burst, float4 coalesced ----
    const int obase = row * ROWLEN + chunk * CHUNK;
    const float4* sout = (const float4*)(s + HALO);
    #pragma unroll
    for (int p = 0; p < 8; p++) {
        int idx = tid + p * THREADS;
        if (idx < NV_OUT)
            *(float4*)(y + obase + idx * 4) = sout[idx];
    }
}

extern "C" void kernel_launch(void* const* d_in, const int* in_sizes, int n_in,
                              void* d_out, int out_size)
{
    const float* x = (const float*)d_in[0];
    float*       y = (float*)d_out;

    const int n    = in_sizes[0];          // 61,440,000
    const int rows = n / ROWLEN;           // 64
    dim3 grid(ROWLEN / CHUNK, rows);       // (125, 64) = 8000 blocks

    deemph_kernel<<<grid, THREADS>>>(x, y);
}